// round 1
// baseline (speedup 1.0000x reference)
#include <cuda_runtime.h>
#include <cstdint>
#include <cstddef>

#define SEQ 4096
#define EMB 200
#define HID 256
#define G3  768

#define EMB_OUT_OFF 0
#define HID_OUT_OFF (SEQ*EMB)                 /* 819200  */
#define LAST_OFF    (HID_OUT_OFF + SEQ*2*HID) /* 2916352 */

// Scratch: precomputed input-side gates. gi[dir][t][row]
// rows 0..511 (r,z gates) have b_ih + b_hh folded in; rows 512..767 (n gate) have only b_ih.
__device__ float g_gi[2][SEQ][G3];

// ---------------------------------------------------------------------------
// Phase 1a: embeddings output = emb_weight[utterance]  (float4 copy)
// ---------------------------------------------------------------------------
__global__ void embed_copy_kernel(const int* __restrict__ tok,
                                  const float* __restrict__ emb,
                                  float4* __restrict__ out4) {
    int i = blockIdx.x * 256 + threadIdx.x;      // over SEQ*50 float4s
    if (i < SEQ * 50) {
        int t  = i / 50;
        int k4 = i - t * 50;
        const float4* row = (const float4*)(emb + (size_t)tok[t] * EMB);
        out4[i] = row[k4];
    }
}

// ---------------------------------------------------------------------------
// Phase 1b: gi GEMM.  gi[dir][t][row] = sum_k emb[tok[t]][k] * w_ih[row][k] + bias
// Tile: 64 timesteps x 64 rows, K=200 in shared (padded stride 204 for banks).
// Micro: 256 threads as 16x16; thread computes 4t x 4r (rows tx, tx+16, tx+32, tx+48).
// ---------------------------------------------------------------------------
#define TT 64
#define RT 64
#define KP 204
#define GI_SMEM ((TT + RT) * KP * 4)

extern "C" __global__ void __launch_bounds__(256)
gi_gemm_kernel(const int* __restrict__ tok,
               const float* __restrict__ emb,
               const float* __restrict__ w_ih1, const float* __restrict__ w_ih2,
               const float* __restrict__ b_ih1, const float* __restrict__ b_ih2,
               const float* __restrict__ b_hh1, const float* __restrict__ b_hh2) {
    extern __shared__ float sm[];
    float* xs = sm;              // [TT][KP]
    float* ws = sm + TT * KP;    // [RT][KP]

    int dir = blockIdx.z;
    const float* w_ih = dir ? w_ih2 : w_ih1;
    const float* b_ih = dir ? b_ih2 : b_ih1;
    const float* b_hh = dir ? b_hh2 : b_hh1;
    float* gi = &g_gi[dir][0][0];

    int t0 = blockIdx.x * TT;
    int r0 = blockIdx.y * RT;
    int tid = threadIdx.x;

    // Load x tile (gathered embedding rows) and w tile, vectorized.
    for (int i = tid; i < TT * 50; i += 256) {
        int tt = i / 50, k4 = i - tt * 50;
        float4 v = ((const float4*)(emb + (size_t)tok[t0 + tt] * EMB))[k4];
        *(float4*)&xs[tt * KP + k4 * 4] = v;
    }
    for (int i = tid; i < RT * 50; i += 256) {
        int rr = i / 50, k4 = i - rr * 50;
        float4 v = ((const float4*)(w_ih + (size_t)(r0 + rr) * EMB))[k4];
        *(float4*)&ws[rr * KP + k4 * 4] = v;
    }
    __syncthreads();

    int tx = tid & 15, ty = tid >> 4;
    int tt0 = ty * 4;

    float acc[4][4];
#pragma unroll
    for (int a = 0; a < 4; a++)
#pragma unroll
        for (int b = 0; b < 4; b++) acc[a][b] = 0.f;

#pragma unroll 2
    for (int k = 0; k < EMB; k += 4) {
        float4 xv[4], wv[4];
#pragma unroll
        for (int a = 0; a < 4; a++) xv[a] = *(const float4*)&xs[(tt0 + a) * KP + k];
#pragma unroll
        for (int b = 0; b < 4; b++) wv[b] = *(const float4*)&ws[(tx + 16 * b) * KP + k];
#pragma unroll
        for (int a = 0; a < 4; a++)
#pragma unroll
            for (int b = 0; b < 4; b++) {
                acc[a][b] = fmaf(xv[a].x, wv[b].x, acc[a][b]);
                acc[a][b] = fmaf(xv[a].y, wv[b].y, acc[a][b]);
                acc[a][b] = fmaf(xv[a].z, wv[b].z, acc[a][b]);
                acc[a][b] = fmaf(xv[a].w, wv[b].w, acc[a][b]);
            }
    }

#pragma unroll
    for (int b = 0; b < 4; b++) {
        int row = r0 + tx + 16 * b;
        float bias = b_ih[row] + (row < 512 ? b_hh[row] : 0.f);  // fold b_hh for r,z only
#pragma unroll
        for (int a = 0; a < 4; a++) {
            int t = t0 + tt0 + a;
            gi[(size_t)t * G3 + row] = acc[a][b] + bias;
        }
    }
}

// ---------------------------------------------------------------------------
// Phase 2: sequential biGRU recurrence.
// 2 clusters of 8 CTAs (one per direction), 256 threads/CTA.
// CTA crank owns h-indices [crank*32, crank*32+32): 96 w_hh rows register-resident.
// Warp w owns 4 h-indices; lane l holds w_hh[row][l+32k] (k=0..7) and h[l+32k].
// Per step: 96 FMAs/thread -> butterfly reduce -> gates on lanes 0..3 ->
// DSMEM broadcast of 32 new h values to all 8 CTAs -> barrier.cluster.
// ---------------------------------------------------------------------------
__device__ __forceinline__ float sigf(float x) { return 1.f / (1.f + __expf(-x)); }
__device__ __forceinline__ float tanhfast(float x) { return 2.f / (1.f + __expf(-2.f * x)) - 1.f; }

extern "C" __global__ void __launch_bounds__(256, 1) __cluster_dims__(8, 1, 1)
gru_rec_kernel(const float* __restrict__ w_hh1, const float* __restrict__ w_hh2,
               const float* __restrict__ b_hh1, const float* __restrict__ b_hh2,
               const float* __restrict__ h01,   const float* __restrict__ h02,
               float* __restrict__ out) {
    __shared__ float hbuf[2][HID];

    unsigned crank;
    asm("mov.u32 %0, %%cluster_ctarank;" : "=r"(crank));
    int dir = (blockIdx.x >= 8) ? 1 : 0;
    const float* w_hh = dir ? w_hh2 : w_hh1;
    const float* b_hh = dir ? b_hh2 : b_hh1;
    const float* h0   = dir ? h02 : h01;
    const float* gi_base = &g_gi[dir][0][0];

    int tid  = threadIdx.x;
    int wid  = tid >> 5;
    int lane = tid & 31;
    int jbase = (int)crank * 32 + wid * 4;   // first of this warp's 4 h-indices

    // Load this thread's 96 weights (coalesced: consecutive lanes -> consecutive cols).
    float wreg[96];
#pragma unroll
    for (int g = 0; g < 3; g++)
#pragma unroll
        for (int q = 0; q < 4; q++)
#pragma unroll
            for (int k = 0; k < 8; k++)
                wreg[(g * 4 + q) * 8 + k] =
                    w_hh[(size_t)(g * 256 + jbase + q) * HID + lane + 32 * k];

    float hreg[8];
#pragma unroll
    for (int k = 0; k < 8; k++) hreg[k] = h0[lane + 32 * k];
    if (tid < HID) hbuf[0][tid] = h0[tid];

    int j = jbase + lane;  // meaningful for lane<4
    float bhn = (lane < 4) ? b_hh[512 + j] : 0.f;  // n-gate bias (NOT foldable)
    __syncthreads();

    unsigned hb0 = (unsigned)__cvta_generic_to_shared(&hbuf[0][0]);

#pragma unroll 1
    for (int s = 0; s < SEQ; s++) {
        int t = dir ? (SEQ - 1 - s) : s;
        const float* gi = gi_base + (size_t)t * G3;

        // Early-issue the small loads; consumed only after the ~400-cycle matvec.
        float gir = 0.f, giz = 0.f, gin = 0.f, hold = 0.f;
        if (lane < 4) {
            gir  = __ldg(gi + j);
            giz  = __ldg(gi + 256 + j);
            gin  = __ldg(gi + 512 + j);
            hold = hbuf[s & 1][j];
        }

        // Matvec: 12 rows x 8 cols, all register operands.
        float acc[12];
#pragma unroll
        for (int i = 0; i < 12; i++) acc[i] = 0.f;
#pragma unroll
        for (int k = 0; k < 8; k++) {
            float hv = hreg[k];
#pragma unroll
            for (int i = 0; i < 12; i++) acc[i] = fmaf(wreg[i * 8 + k], hv, acc[i]);
        }

        // Butterfly reduce each row across 32 lanes (12 independent chains).
#pragma unroll
        for (int i = 0; i < 12; i++) {
            float a = acc[i];
            a += __shfl_xor_sync(0xffffffffu, a, 16);
            a += __shfl_xor_sync(0xffffffffu, a, 8);
            a += __shfl_xor_sync(0xffffffffu, a, 4);
            a += __shfl_xor_sync(0xffffffffu, a, 2);
            a += __shfl_xor_sync(0xffffffffu, a, 1);
            acc[i] = a;
        }

        if (lane < 4) {
            float ar = lane == 0 ? acc[0] : lane == 1 ? acc[1] : lane == 2 ? acc[2] : acc[3];
            float az = lane == 0 ? acc[4] : lane == 1 ? acc[5] : lane == 2 ? acc[6] : acc[7];
            float an = lane == 0 ? acc[8] : lane == 1 ? acc[9] : lane == 2 ? acc[10] : acc[11];

            float r  = sigf(gir + ar);            // b_hh_r already folded into gir
            float z  = sigf(giz + az);            // b_hh_z folded into giz
            float n  = tanhfast(gin + r * (an + bhn));
            float hn = n + z * (hold - n);        // (1-z)*n + z*h

            out[HID_OUT_OFF + (size_t)t * 512 + dir * HID + j] = hn;
            if (s == SEQ - 1) out[LAST_OFF + dir * HID + j] = hn;

            // Broadcast to every CTA in the cluster (including self), next parity.
            unsigned dst = hb0 + (((unsigned)((s + 1) & 1)) * HID + (unsigned)j) * 4u;
#pragma unroll
            for (int rk = 0; rk < 8; rk++) {
                asm volatile(
                    "{\n\t.reg .u32 ra;\n\t"
                    "mapa.shared::cluster.u32 ra, %0, %1;\n\t"
                    "st.shared::cluster.f32 [ra], %2;\n\t}"
                    :: "r"(dst), "r"(rk), "f"(hn) : "memory");
            }
        }

        // Release our DSMEM stores; acquire everyone else's.
        asm volatile("barrier.cluster.arrive.aligned;" ::: "memory");
        asm volatile("barrier.cluster.wait.aligned;"   ::: "memory");

        int p = (s + 1) & 1;
#pragma unroll
        for (int k = 0; k < 8; k++) hreg[k] = hbuf[p][lane + 32 * k];
    }
}

// ---------------------------------------------------------------------------
// Launcher
// ---------------------------------------------------------------------------
extern "C" void kernel_launch(void* const* d_in, const int* in_sizes, int n_in,
                              void* d_out, int out_size) {
    const int*   tok     = (const int*)  d_in[0];
    const float* hidden  = (const float*)d_in[1];
    const float* hidden2 = (const float*)d_in[2];
    const float* emb     = (const float*)d_in[3];
    const float* w_ih1   = (const float*)d_in[4];
    const float* w_hh1   = (const float*)d_in[5];
    const float* b_ih1   = (const float*)d_in[6];
    const float* b_hh1   = (const float*)d_in[7];
    const float* w_ih2   = (const float*)d_in[8];
    const float* w_hh2   = (const float*)d_in[9];
    const float* b_ih2   = (const float*)d_in[10];
    const float* b_hh2   = (const float*)d_in[11];
    float* out = (float*)d_out;

    // Phase 1a: embeddings output (SEQ*200 floats = SEQ*50 float4s)
    embed_copy_kernel<<<(SEQ * 50 + 255) / 256, 256>>>(tok, emb, (float4*)out);

    // Phase 1b: gi GEMM (needs >48KB dynamic smem; idempotent attribute set)
    cudaFuncSetAttribute(gi_gemm_kernel,
                         cudaFuncAttributeMaxDynamicSharedMemorySize, GI_SMEM);
    gi_gemm_kernel<<<dim3(SEQ / TT, G3 / RT, 2), 256, GI_SMEM>>>(
        tok, emb, w_ih1, w_ih2, b_ih1, b_ih2, b_hh1, b_hh2);

    // Phase 2: recurrence — 2 clusters x 8 CTAs
    gru_rec_kernel<<<16, 256>>>(w_hh1, w_hh2, b_hh1, b_hh2, hidden, hidden2, out);
}